// round 1
// baseline (speedup 1.0000x reference)
#include <cuda_runtime.h>
#include <cuda_bf16.h>
#include <cstdint>

#define EPSV 1e-9f
#define TOPK 13
#define MAXL 8448
#define MAXBL (32 * 8400)
#define MAXBN 2048
#define TPB 256

// ---------------- device scratch (no allocation allowed) ----------------
__device__ unsigned long long g_topk_mask[MAXBL];  // bit j set => anchor i in topk of gt j
__device__ int g_assigned[MAXBL];                  // final single assigned gt (-1 if none)
__device__ float g_align_sel[MAXBL];               // align value at assigned gt
__device__ unsigned int g_max_metrics[MAXBN];      // float bits, per (b, j)
__device__ unsigned int g_max_ious[MAXBN];         // float bits, per (b, j)

// ---------------- init ----------------
__global__ void init_kernel(int BL, int Bn) {
    int i = blockIdx.x * blockDim.x + threadIdx.x;
    if (i < BL) g_topk_mask[i] = 0ull;
    if (i < Bn) { g_max_metrics[i] = 0u; g_max_ious[i] = 0u; }
}

// ---------------- kernel A: per-(b,j) top-13 over L anchors ----------------
__global__ __launch_bounds__(TPB) void topk_kernel(
    const float* __restrict__ pred_scores,   // (B,L,C)
    const float* __restrict__ pred_bboxes,   // (B,L,4)
    const float* __restrict__ anchors,       // (L,2)
    const int*   __restrict__ gt_labels,     // (B,n,1)
    const float* __restrict__ gt_bboxes,     // (B,n,4)
    const float* __restrict__ pad_mask,      // (B,n,1)
    int B, int L, int C, int n)
{
    int row = blockIdx.x;          // b*n + j
    int b = row / n;
    int j = row - b * n;
    if (pad_mask[row] <= 0.0f) return;   // row contributes no topk bits

    __shared__ float sval[MAXL];
    __shared__ float rval[TPB];
    __shared__ int   ridx[TPB];

    const float4 g = __ldg((const float4*)gt_bboxes + row);
    const float garea = (g.z - g.x) * (g.w - g.y);
    const int label = gt_labels[row];

    const float4* pb = (const float4*)pred_bboxes + (size_t)b * L;
    const float*  ps = pred_scores + (size_t)b * L * C;
    const float2* ap = (const float2*)anchors;

    for (int i = threadIdx.x; i < L; i += TPB) {
        float4 p = pb[i];
        float iw = fmaxf(fminf(g.z, p.z) - fmaxf(g.x, p.x), 0.0f);
        float ih = fmaxf(fminf(g.w, p.w) - fmaxf(g.y, p.y), 0.0f);
        float inter = iw * ih;
        float parea = (p.z - p.x) * (p.w - p.y);
        float iou = inter / (garea + parea - inter + EPSV);
        float cls = ps[(size_t)i * C + label];
        float i2 = iou * iou;
        float align = cls * (i2 * i2 * i2);
        float2 a = ap[i];
        float d = fminf(fminf(a.x - g.x, a.y - g.y), fminf(g.z - a.x, g.w - a.y));
        sval[i] = (d > EPSV) ? align : 0.0f;
    }
    __syncthreads();

    // 13 rounds of block argmax with XLA tie-break (value desc, index asc)
    for (int t = 0; t < TOPK; t++) {
        float bv = -2.0f; int bi = 0x7fffffff;
        for (int i = threadIdx.x; i < L; i += TPB) {
            float v = sval[i];
            if (v > bv || (v == bv && i < bi)) { bv = v; bi = i; }
        }
        rval[threadIdx.x] = bv; ridx[threadIdx.x] = bi;
        __syncthreads();
        for (int s = TPB / 2; s > 0; s >>= 1) {
            if (threadIdx.x < s) {
                float v = rval[threadIdx.x + s]; int ii = ridx[threadIdx.x + s];
                if (v > rval[threadIdx.x] || (v == rval[threadIdx.x] && ii < ridx[threadIdx.x])) {
                    rval[threadIdx.x] = v; ridx[threadIdx.x] = ii;
                }
            }
            __syncthreads();
        }
        if (threadIdx.x == 0) {
            int w = ridx[0];
            sval[w] = -1.0f;   // exclude for next round
            atomicOr(&g_topk_mask[(size_t)b * L + w], 1ull << j);
        }
        __syncthreads();
    }
}

// ---------------- kernel B: resolve single assignment per anchor ----------------
__global__ __launch_bounds__(TPB) void assign_kernel(
    const float* __restrict__ pred_scores,
    const float* __restrict__ pred_bboxes,
    const float* __restrict__ anchors,
    const int*   __restrict__ gt_labels,
    const float* __restrict__ gt_bboxes,
    const float* __restrict__ pad_mask,
    int B, int L, int C, int n)
{
    int b = blockIdx.y;
    int i = blockIdx.x * blockDim.x + threadIdx.x;

    __shared__ float4 sgt[64];
    __shared__ float  spad[64];
    for (int j = threadIdx.x; j < n; j += blockDim.x) {
        sgt[j]  = ((const float4*)gt_bboxes)[(size_t)b * n + j];
        spad[j] = pad_mask[b * n + j];
    }
    __syncthreads();
    if (i >= L) return;

    float4 p = ((const float4*)pred_bboxes)[(size_t)b * L + i];
    float parea = (p.z - p.x) * (p.w - p.y);
    float2 a = ((const float2*)anchors)[i];
    unsigned long long tmask = g_topk_mask[(size_t)b * L + i];

    int cnt = 0, pos_j = -1; float pos_iou = 0.0f;
    float best_iou = -1.0f; int best_j = 0;

    for (int j = 0; j < n; j++) {
        float4 g = sgt[j];
        float iw = fmaxf(fminf(g.z, p.z) - fmaxf(g.x, p.x), 0.0f);
        float ih = fmaxf(fminf(g.w, p.w) - fmaxf(g.y, p.y), 0.0f);
        float inter = iw * ih;
        float garea = (g.z - g.x) * (g.w - g.y);
        float iou = inter / (garea + parea - inter + EPSV);
        if (iou > best_iou) { best_iou = iou; best_j = j; }   // first-argmax
        float d = fminf(fminf(a.x - g.x, a.y - g.y), fminf(g.z - a.x, g.w - a.y));
        bool ing = (d > EPSV);
        if (((tmask >> j) & 1ull) && ing && spad[j] > 0.0f) {
            cnt++; pos_j = j; pos_iou = iou;
        }
    }

    size_t idx = (size_t)b * L + i;
    if (cnt == 0) {
        g_assigned[idx] = -1;
        g_align_sel[idx] = 0.0f;
        return;
    }
    int aj; float iou;
    if (cnt == 1) { aj = pos_j; iou = pos_iou; }
    else          { aj = best_j; iou = best_iou; }   // mps>1 -> is_max_iou column

    int label = gt_labels[b * n + aj];
    float cls = pred_scores[idx * C + label];
    float i2 = iou * iou;
    float align = cls * (i2 * i2 * i2);

    g_assigned[idx] = aj;
    g_align_sel[idx] = align;
    atomicMax((int*)&g_max_metrics[b * n + aj], __float_as_int(align));
    atomicMax((int*)&g_max_ious[b * n + aj],   __float_as_int(iou));
}

// ---------------- kernel C: gather + write outputs ----------------
__global__ __launch_bounds__(TPB) void output_kernel(
    const int*   __restrict__ gt_labels,
    const float* __restrict__ gt_bboxes,
    const float* __restrict__ gt_poses,
    const int*   __restrict__ bg_ptr,     // may be null
    float* __restrict__ out,
    int B, int L, int C, int n, int K)
{
    size_t idx = (size_t)blockIdx.x * blockDim.x + threadIdx.x;
    size_t BL = (size_t)B * L;
    if (idx >= BL) return;
    int b = (int)(idx / L);

    int bg = bg_ptr ? *bg_ptr : 1;
    int aj = g_assigned[idx];
    int agi = (aj < 0) ? 0 : aj;
    int label = (aj < 0) ? bg : gt_labels[b * n + agi];

    float s = 0.0f;
    if (aj >= 0) {
        float mm = __int_as_float((int)g_max_metrics[b * n + aj]);
        float mi = __int_as_float((int)g_max_ious[b * n + aj]);
        s = g_align_sel[idx] / (mm + EPSV) * mi;
    }

    size_t off_lab  = 0;
    size_t off_box  = off_lab + BL;
    size_t off_pose = off_box + 4 * BL;
    size_t off_sc   = off_pose + BL * (size_t)(K * 3);
    size_t off_agi  = off_sc + BL * (size_t)C;

    out[off_lab + idx] = (float)label;

    float4 gb = ((const float4*)gt_bboxes)[(size_t)b * n + agi];
    float* ob = out + off_box + idx * 4;
    ob[0] = gb.x; ob[1] = gb.y; ob[2] = gb.z; ob[3] = gb.w;

    const float* gp = gt_poses + ((size_t)b * n + agi) * (size_t)(K * 3);
    float* op = out + off_pose + idx * (size_t)(K * 3);
    #pragma unroll
    for (int t = 0; t < 51; t++) op[t] = gp[t];

    float* os = out + off_sc + idx * (size_t)C;
    int m = 0;
    for (int c = 0; c <= C; c++) {
        if (c == bg) continue;
        os[m] = (label == c) ? s : 0.0f;
        m++;
    }

    out[off_agi + idx] = (float)(agi + b * n);
}

// ---------------- launcher ----------------
extern "C" void kernel_launch(void* const* d_in, const int* in_sizes, int n_in,
                              void* d_out, int out_size)
{
    const float* pred_scores = (const float*)d_in[0];
    const float* pred_bboxes = (const float*)d_in[1];
    // d_in[2] pred_poses: unused by the reference
    const float* anchors     = (const float*)d_in[3];
    const int*   gt_labels   = (const int*)d_in[4];
    const float* gt_bboxes   = (const float*)d_in[5];
    const float* gt_poses    = (const float*)d_in[6];
    const float* pad_mask    = (const float*)d_in[7];
    const int*   bg_ptr      = (n_in > 8) ? (const int*)d_in[8] : nullptr;

    int L = in_sizes[3] / 2;
    int B = in_sizes[1] / (4 * L);
    int C = in_sizes[0] / (B * L);
    int K = in_sizes[2] / (B * L * 3);
    int n = in_sizes[5] / (B * 4);

    int BL = B * L;
    int Bn = B * n;

    {
        int tot = BL;
        init_kernel<<<(tot + TPB - 1) / TPB, TPB>>>(BL, Bn);
    }

    topk_kernel<<<Bn, TPB>>>(pred_scores, pred_bboxes, anchors,
                             gt_labels, gt_bboxes, pad_mask, B, L, C, n);

    dim3 gridB((L + TPB - 1) / TPB, B);
    assign_kernel<<<gridB, TPB>>>(pred_scores, pred_bboxes, anchors,
                                  gt_labels, gt_bboxes, pad_mask, B, L, C, n);

    output_kernel<<<(BL + TPB - 1) / TPB, TPB>>>(gt_labels, gt_bboxes, gt_poses,
                                                 bg_ptr, (float*)d_out,
                                                 B, L, C, n, K);
}

// round 2
// speedup vs baseline: 1.2965x; 1.2965x over previous
#include <cuda_runtime.h>
#include <cuda_bf16.h>
#include <cstdint>

#define EPSV 1e-9f
#define TOPK 13
#define MAXBL (32 * 8400)
#define MAXBN 2048
#define TPB 256

// ---------------- device scratch (no allocation allowed) ----------------
__device__ unsigned long long g_topk_mask[MAXBL];  // bit j set => anchor i in topk of gt j
__device__ int g_assigned[MAXBL];                  // final single assigned gt (-1 if none)
__device__ float g_align_sel[MAXBL];               // align value at assigned gt
__device__ unsigned int g_max_metrics[MAXBN];      // float bits, per (b, j)
__device__ unsigned int g_max_ious[MAXBN];         // float bits, per (b, j)

// ---------------- init ----------------
__global__ void init_kernel(int BL, int Bn) {
    int i = blockIdx.x * blockDim.x + threadIdx.x;
    if (i < BL) g_topk_mask[i] = 0ull;
    if (i < Bn) { g_max_metrics[i] = 0u; g_max_ious[i] = 0u; }
}

// ---------------- kernel A: per-(b,j) top-13 over L anchors ----------------
// Per-thread register top-13 (value desc, index asc) + 13 rounds of
// warp-shuffle tournament over per-thread heads.
__global__ __launch_bounds__(TPB) void topk_kernel(
    const float* __restrict__ pred_scores,   // (B,L,C)
    const float* __restrict__ pred_bboxes,   // (B,L,4)
    const float* __restrict__ anchors,       // (L,2)
    const int*   __restrict__ gt_labels,     // (B,n,1)
    const float* __restrict__ gt_bboxes,     // (B,n,4)
    const float* __restrict__ pad_mask,      // (B,n,1)
    int B, int L, int C, int n)
{
    int row = blockIdx.x;          // b*n + j
    int b = row / n;
    int j = row - b * n;
    if (pad_mask[row] <= 0.0f) return;   // row contributes no topk bits

    const float4 g = __ldg((const float4*)gt_bboxes + row);
    const float garea = (g.z - g.x) * (g.w - g.y);
    const int label = gt_labels[row];

    const float4* pb = (const float4*)pred_bboxes + (size_t)b * L;
    const float*  ps = pred_scores + (size_t)b * L * C;
    const float2* ap = (const float2*)anchors;

    // local top-13, sorted desc by value; ties: earlier (smaller) index first.
    float lv[TOPK];
    int   li[TOPK];
    #pragma unroll
    for (int t = 0; t < TOPK; t++) { lv[t] = -1.0f; li[t] = 0x7fffffff; }

    for (int i = threadIdx.x; i < L; i += TPB) {
        float4 p = pb[i];
        float iw = fmaxf(fminf(g.z, p.z) - fmaxf(g.x, p.x), 0.0f);
        float ih = fmaxf(fminf(g.w, p.w) - fmaxf(g.y, p.y), 0.0f);
        float inter = iw * ih;
        float parea = (p.z - p.x) * (p.w - p.y);
        float iou = inter / (garea + parea - inter + EPSV);
        float cls = ps[(size_t)i * C + label];
        float i2 = iou * iou;
        float align = cls * (i2 * i2 * i2);
        float2 a = ap[i];
        float d = fminf(fminf(a.x - g.x, a.y - g.y), fminf(g.z - a.x, g.w - a.y));
        float v = (d > EPSV) ? align : 0.0f;

        if (v > lv[TOPK - 1]) {          // strict >: equal values keep earlier index
            lv[TOPK - 1] = v; li[TOPK - 1] = i;
            #pragma unroll
            for (int t = TOPK - 1; t > 0; t--) {
                if (lv[t] > lv[t - 1]) {
                    float tv = lv[t]; lv[t] = lv[t - 1]; lv[t - 1] = tv;
                    int   ti = li[t]; li[t] = li[t - 1]; li[t - 1] = ti;
                }
            }
        }
    }

    // tournament: 13 rounds of block-max over per-thread heads.
    // key = (value_bits << 32) | (MAX - index): value desc, index asc.
    // all values >= 0 so float bits are monotone.
    __shared__ unsigned long long swmax[TPB / 32];
    __shared__ unsigned long long sbest;
    int lane = threadIdx.x & 31;
    int wid  = threadIdx.x >> 5;

    for (int t = 0; t < TOPK; t++) {
        unsigned long long key =
            ((unsigned long long)__float_as_uint(fmaxf(lv[0], 0.0f)) << 32) |
            (unsigned int)(0x7fffffff - li[0]);
        // threads whose list is somehow exhausted (cannot happen: >=32 elems each)
        // would carry value 0 with huge index -> never win over real entries.
        unsigned long long k = key;
        #pragma unroll
        for (int s = 16; s > 0; s >>= 1) {
            unsigned long long o = __shfl_xor_sync(0xffffffffu, k, s);
            if (o > k) k = o;
        }
        if (lane == 0) swmax[wid] = k;
        __syncthreads();
        if (threadIdx.x == 0) {
            unsigned long long bm = swmax[0];
            #pragma unroll
            for (int w = 1; w < TPB / 32; w++) if (swmax[w] > bm) bm = swmax[w];
            sbest = bm;
        }
        __syncthreads();
        if (key == sbest && lv[0] >= 0.0f) {
            atomicOr(&g_topk_mask[(size_t)b * L + li[0]], 1ull << j);
            #pragma unroll
            for (int t2 = 0; t2 < TOPK - 1; t2++) { lv[t2] = lv[t2 + 1]; li[t2] = li[t2 + 1]; }
            lv[TOPK - 1] = -1.0f; li[TOPK - 1] = 0x7fffffff;
        }
        __syncthreads();
    }
}

// ---------------- kernel B: resolve single assignment per anchor ----------------
__global__ __launch_bounds__(TPB) void assign_kernel(
    const float* __restrict__ pred_scores,
    const float* __restrict__ pred_bboxes,
    const float* __restrict__ anchors,
    const int*   __restrict__ gt_labels,
    const float* __restrict__ gt_bboxes,
    const float* __restrict__ pad_mask,
    int B, int L, int C, int n)
{
    int b = blockIdx.y;
    int i = blockIdx.x * blockDim.x + threadIdx.x;

    __shared__ float4 sgt[64];
    __shared__ float  spad[64];
    for (int j = threadIdx.x; j < n; j += blockDim.x) {
        sgt[j]  = ((const float4*)gt_bboxes)[(size_t)b * n + j];
        spad[j] = pad_mask[b * n + j];
    }
    __syncthreads();
    if (i >= L) return;

    float4 p = ((const float4*)pred_bboxes)[(size_t)b * L + i];
    float parea = (p.z - p.x) * (p.w - p.y);
    float2 a = ((const float2*)anchors)[i];
    unsigned long long tmask = g_topk_mask[(size_t)b * L + i];

    int cnt = 0, pos_j = -1; float pos_iou = 0.0f;
    float best_iou = -1.0f; int best_j = 0;

    for (int j = 0; j < n; j++) {
        float4 g = sgt[j];
        float iw = fmaxf(fminf(g.z, p.z) - fmaxf(g.x, p.x), 0.0f);
        float ih = fmaxf(fminf(g.w, p.w) - fmaxf(g.y, p.y), 0.0f);
        float inter = iw * ih;
        float garea = (g.z - g.x) * (g.w - g.y);
        float iou = inter / (garea + parea - inter + EPSV);
        if (iou > best_iou) { best_iou = iou; best_j = j; }   // first-argmax
        float d = fminf(fminf(a.x - g.x, a.y - g.y), fminf(g.z - a.x, g.w - a.y));
        bool ing = (d > EPSV);
        if (((tmask >> j) & 1ull) && ing && spad[j] > 0.0f) {
            cnt++; pos_j = j; pos_iou = iou;
        }
    }

    size_t idx = (size_t)b * L + i;
    if (cnt == 0) {
        g_assigned[idx] = -1;
        g_align_sel[idx] = 0.0f;
        return;
    }
    int aj; float iou;
    if (cnt == 1) { aj = pos_j; iou = pos_iou; }
    else          { aj = best_j; iou = best_iou; }   // mps>1 -> is_max_iou column

    int label = gt_labels[b * n + aj];
    float cls = pred_scores[idx * C + label];
    float i2 = iou * iou;
    float align = cls * (i2 * i2 * i2);

    g_assigned[idx] = aj;
    g_align_sel[idx] = align;
    atomicMax((int*)&g_max_metrics[b * n + aj], __float_as_int(align));
    atomicMax((int*)&g_max_ious[b * n + aj],   __float_as_int(iou));
}

// ---------------- kernel C1: per-anchor small outputs ----------------
__global__ __launch_bounds__(TPB) void output_small_kernel(
    const int*   __restrict__ gt_labels,
    const float* __restrict__ gt_bboxes,
    const int*   __restrict__ bg_ptr,     // may be null
    float* __restrict__ out,
    int B, int L, int C, int n, int K)
{
    size_t idx = (size_t)blockIdx.x * blockDim.x + threadIdx.x;
    size_t BL = (size_t)B * L;
    if (idx >= BL) return;
    int b = (int)(idx / L);

    int bg = bg_ptr ? *bg_ptr : 1;
    int aj = g_assigned[idx];
    int agi = (aj < 0) ? 0 : aj;
    int label = (aj < 0) ? bg : gt_labels[b * n + agi];

    float s = 0.0f;
    if (aj >= 0) {
        float mm = __int_as_float((int)g_max_metrics[b * n + aj]);
        float mi = __int_as_float((int)g_max_ious[b * n + aj]);
        s = g_align_sel[idx] / (mm + EPSV) * mi;
    }

    size_t off_lab  = 0;
    size_t off_box  = off_lab + BL;
    size_t off_pose = off_box + 4 * BL;
    size_t off_sc   = off_pose + BL * (size_t)(K * 3);
    size_t off_agi  = off_sc + BL * (size_t)C;

    out[off_lab + idx] = (float)label;

    float4 gb = ((const float4*)gt_bboxes)[(size_t)b * n + agi];
    ((float4*)(out + off_box))[idx] = gb;

    float* os = out + off_sc + idx * (size_t)C;
    int m = 0;
    for (int c = 0; c <= C; c++) {
        if (c == bg) continue;
        os[m] = (label == c) ? s : 0.0f;
        m++;
    }

    out[off_agi + idx] = (float)(agi + b * n);
}

// ---------------- kernel C2: coalesced pose gather-copy ----------------
__global__ __launch_bounds__(TPB) void output_pose_kernel(
    const float* __restrict__ gt_poses,
    float* __restrict__ out,
    int B, int L, int n, int K3)
{
    size_t BL = (size_t)B * L;
    size_t total = BL * (size_t)K3;
    size_t e = (size_t)blockIdx.x * blockDim.x + threadIdx.x;
    if (e >= total) return;

    size_t idx = e / (size_t)K3;          // anchor
    int t = (int)(e - idx * (size_t)K3);  // pose element
    int b = (int)(idx / L);

    int aj = g_assigned[idx];
    int agi = (aj < 0) ? 0 : aj;

    size_t off_pose = BL * 5;             // after labels (BL) + boxes (4*BL)
    out[off_pose + e] = gt_poses[((size_t)b * n + agi) * (size_t)K3 + t];
}

// ---------------- launcher ----------------
extern "C" void kernel_launch(void* const* d_in, const int* in_sizes, int n_in,
                              void* d_out, int out_size)
{
    const float* pred_scores = (const float*)d_in[0];
    const float* pred_bboxes = (const float*)d_in[1];
    // d_in[2] pred_poses: unused by the reference
    const float* anchors     = (const float*)d_in[3];
    const int*   gt_labels   = (const int*)d_in[4];
    const float* gt_bboxes   = (const float*)d_in[5];
    const float* gt_poses    = (const float*)d_in[6];
    const float* pad_mask    = (const float*)d_in[7];
    const int*   bg_ptr      = (n_in > 8) ? (const int*)d_in[8] : nullptr;

    int L = in_sizes[3] / 2;
    int B = in_sizes[1] / (4 * L);
    int C = in_sizes[0] / (B * L);
    int K = in_sizes[2] / (B * L * 3);
    int n = in_sizes[5] / (B * 4);

    int BL = B * L;
    int Bn = B * n;

    init_kernel<<<(BL + TPB - 1) / TPB, TPB>>>(BL, Bn);

    topk_kernel<<<Bn, TPB>>>(pred_scores, pred_bboxes, anchors,
                             gt_labels, gt_bboxes, pad_mask, B, L, C, n);

    dim3 gridB((L + TPB - 1) / TPB, B);
    assign_kernel<<<gridB, TPB>>>(pred_scores, pred_bboxes, anchors,
                                  gt_labels, gt_bboxes, pad_mask, B, L, C, n);

    output_small_kernel<<<(BL + TPB - 1) / TPB, TPB>>>(gt_labels, gt_bboxes,
                                                       bg_ptr, (float*)d_out,
                                                       B, L, C, n, K);

    size_t pose_total = (size_t)BL * (size_t)(K * 3);
    int pose_blocks = (int)((pose_total + TPB - 1) / TPB);
    output_pose_kernel<<<pose_blocks, TPB>>>(gt_poses, (float*)d_out,
                                             B, L, n, K * 3);
}

// round 3
// speedup vs baseline: 1.8474x; 1.4249x over previous
#include <cuda_runtime.h>
#include <cuda_bf16.h>
#include <cstdint>

#define EPSV 1e-9f
#define TOPK 13
#define MAXBL (32 * 8400)
#define MAXBN 2048
#define CAP 512
#define TPB 256

// ---------------- device scratch (no allocation allowed) ----------------
__device__ unsigned long long g_topk_mask[MAXBL];   // bit j set => anchor i in topk of gt j
__device__ int g_assigned[MAXBL];                   // final single assigned gt (-1 if none)
__device__ float g_align_sel[MAXBL];                // align value at assigned gt
__device__ unsigned int g_max_metrics[MAXBN];       // float bits, per (b, j)
__device__ unsigned int g_max_ious[MAXBN];          // float bits, per (b, j)
__device__ unsigned long long g_cand[(size_t)MAXBN * CAP];  // packed (val, idx) keys
__device__ int g_cnt[MAXBN];                        // candidate count per row
__device__ int g_ovf[MAXBN];                        // overflow flag per row

// ---------------- init ----------------
__global__ void init_kernel(int BL, int Bn) {
    int i = blockIdx.x * blockDim.x + threadIdx.x;
    if (i < BL) g_topk_mask[i] = 0ull;
    if (i < Bn) {
        g_max_metrics[i] = 0u; g_max_ious[i] = 0u;
        g_cnt[i] = 0; g_ovf[i] = 0;
    }
}

// ---------------- kernel A1: candidate compaction (anchor-parallel) ----------------
__global__ __launch_bounds__(TPB) void cand_kernel(
    const float* __restrict__ pred_scores,   // (B,L,C)
    const float* __restrict__ pred_bboxes,   // (B,L,4)
    const float* __restrict__ anchors,       // (L,2)
    const int*   __restrict__ gt_labels,     // (B,n,1)
    const float* __restrict__ gt_bboxes,     // (B,n,4)
    const float* __restrict__ pad_mask,      // (B,n,1)
    int B, int L, int C, int n)
{
    int b = blockIdx.y;
    int i = blockIdx.x * blockDim.x + threadIdx.x;

    __shared__ float4 sgt[64];
    __shared__ float  spad[64];
    __shared__ int    slab[64];
    for (int j = threadIdx.x; j < n; j += blockDim.x) {
        sgt[j]  = ((const float4*)gt_bboxes)[(size_t)b * n + j];
        spad[j] = pad_mask[b * n + j];
        slab[j] = gt_labels[b * n + j];
    }
    __syncthreads();
    if (i >= L) return;

    float4 p = ((const float4*)pred_bboxes)[(size_t)b * L + i];
    float parea = (p.z - p.x) * (p.w - p.y);
    float2 a = ((const float2*)anchors)[i];
    const float* psb = pred_scores + ((size_t)b * L + i) * C;

    unsigned int enc_i = 0x7fffffffu - (unsigned int)i;

    for (int j = 0; j < n; j++) {
        if (spad[j] <= 0.0f) continue;
        float4 g = sgt[j];
        float d = fminf(fminf(a.x - g.x, a.y - g.y), fminf(g.z - a.x, g.w - a.y));
        if (d <= EPSV) continue;                      // not in gts -> metric 0
        float iw = fmaxf(fminf(g.z, p.z) - fmaxf(g.x, p.x), 0.0f);
        float ih = fmaxf(fminf(g.w, p.w) - fmaxf(g.y, p.y), 0.0f);
        float inter = iw * ih;
        float garea = (g.z - g.x) * (g.w - g.y);
        float iou = inter / (garea + parea - inter + EPSV);
        float cls = psb[slab[j]];
        float i2 = iou * iou;
        float v = cls * (i2 * i2 * i2);
        if (v > 0.0f) {
            int row = b * n + j;
            int pos = atomicAdd(&g_cnt[row], 1);
            if (pos < CAP) {
                unsigned long long key =
                    ((unsigned long long)__float_as_uint(v) << 32) | enc_i;
                g_cand[(size_t)row * CAP + pos] = key;
            }
        }
    }
}

// ---------------- kernel A2: per-row top-13 select (one warp per (b,j)) ----------------
__global__ __launch_bounds__(TPB) void select_kernel(
    const float* __restrict__ pad_mask, int B, int L, int n)
{
    int wid  = threadIdx.x >> 5;
    int lane = threadIdx.x & 31;
    int r = blockIdx.x * (TPB / 32) + wid;
    __shared__ unsigned int bm[TPB / 32][20];   // 640-bit index bitmap per warp
    if (r >= B * n) return;
    if (pad_mask[r] <= 0.0f) return;            // padded row -> no topk bits

    int c = g_cnt[r];
    if (c > CAP) { if (lane == 0) g_ovf[r] = 1; return; }   // fallback handles

    int b = r / n;
    int j = r - b * n;
    unsigned long long jbit = 1ull << j;
    const unsigned long long* buf = g_cand + (size_t)r * CAP;

    unsigned long long ck[CAP / 32];
    #pragma unroll
    for (int s = 0; s < CAP / 32; s++) {
        int idx = s * 32 + lane;
        ck[s] = (idx < c) ? buf[idx] : 0ull;
    }

    // bitmap of candidate indices < 640 (for exact zero-metric tie fill)
    for (int w = lane; w < 20; w += 32) bm[wid][w] = 0u;
    __syncwarp();
    #pragma unroll
    for (int s = 0; s < CAP / 32; s++) {
        if (ck[s]) {
            unsigned int ai = 0x7fffffffu - (unsigned int)(ck[s] & 0xffffffffu);
            if (ai < 640u) atomicOr(&bm[wid][ai >> 5], 1u << (ai & 31u));
        }
    }
    __syncwarp();

    // 13 rounds of warp argmax (value desc, index asc) over positives
    int p = 0;
    for (int t = 0; t < TOPK; t++) {
        unsigned long long m = 0ull;
        #pragma unroll
        for (int s = 0; s < CAP / 32; s++) if (ck[s] > m) m = ck[s];
        #pragma unroll
        for (int sh = 16; sh > 0; sh >>= 1) {
            unsigned long long o = __shfl_xor_sync(0xffffffffu, m, sh);
            if (o > m) m = o;
        }
        if (m == 0ull) break;       // positives exhausted
        p++;
        #pragma unroll
        for (int s = 0; s < CAP / 32; s++) {
            if (ck[s] == m) {       // keys unique (index embedded)
                ck[s] = 0ull;
                unsigned int ai = 0x7fffffffu - (unsigned int)(m & 0xffffffffu);
                atomicOr(&g_topk_mask[(size_t)b * L + ai], jbit);
            }
        }
    }

    // zero-metric tie fill: smallest indices with metric == 0
    if (lane == 0) {
        int rem = TOPK - p;
        int i = 0;
        while (rem > 0 && i < 640) {
            if (!((bm[wid][i >> 5] >> (i & 31u)) & 1u)) {
                atomicOr(&g_topk_mask[(size_t)b * L + i], jbit);
                rem--;
            }
            i++;
        }
    }
}

// ---------------- kernel A3: full-scan fallback for overflow rows ----------------
__global__ __launch_bounds__(TPB) void topk_fallback_kernel(
    const float* __restrict__ pred_scores,
    const float* __restrict__ pred_bboxes,
    const float* __restrict__ anchors,
    const int*   __restrict__ gt_labels,
    const float* __restrict__ gt_bboxes,
    int B, int L, int C, int n)
{
    int row = blockIdx.x;
    if (!g_ovf[row]) return;       // almost always exits immediately
    int b = row / n;
    int j = row - b * n;

    const float4 g = __ldg((const float4*)gt_bboxes + row);
    const float garea = (g.z - g.x) * (g.w - g.y);
    const int label = gt_labels[row];

    const float4* pb = (const float4*)pred_bboxes + (size_t)b * L;
    const float*  ps = pred_scores + (size_t)b * L * C;
    const float2* ap = (const float2*)anchors;

    float lv[TOPK]; int li[TOPK];
    #pragma unroll
    for (int t = 0; t < TOPK; t++) { lv[t] = -1.0f; li[t] = 0x7fffffff; }

    for (int i = threadIdx.x; i < L; i += TPB) {
        float4 p = pb[i];
        float iw = fmaxf(fminf(g.z, p.z) - fmaxf(g.x, p.x), 0.0f);
        float ih = fmaxf(fminf(g.w, p.w) - fmaxf(g.y, p.y), 0.0f);
        float inter = iw * ih;
        float parea = (p.z - p.x) * (p.w - p.y);
        float iou = inter / (garea + parea - inter + EPSV);
        float cls = ps[(size_t)i * C + label];
        float i2 = iou * iou;
        float align = cls * (i2 * i2 * i2);
        float2 a = ap[i];
        float d = fminf(fminf(a.x - g.x, a.y - g.y), fminf(g.z - a.x, g.w - a.y));
        float v = (d > EPSV) ? align : 0.0f;

        if (v > lv[TOPK - 1]) {
            lv[TOPK - 1] = v; li[TOPK - 1] = i;
            #pragma unroll
            for (int t = TOPK - 1; t > 0; t--) {
                if (lv[t] > lv[t - 1]) {
                    float tv = lv[t]; lv[t] = lv[t - 1]; lv[t - 1] = tv;
                    int   ti = li[t]; li[t] = li[t - 1]; li[t - 1] = ti;
                }
            }
        }
    }

    __shared__ unsigned long long swmax[TPB / 32];
    __shared__ unsigned long long sbest;
    int lane = threadIdx.x & 31;
    int wid  = threadIdx.x >> 5;

    for (int t = 0; t < TOPK; t++) {
        unsigned long long key =
            ((unsigned long long)__float_as_uint(fmaxf(lv[0], 0.0f)) << 32) |
            (unsigned int)(0x7fffffff - li[0]);
        unsigned long long k = key;
        #pragma unroll
        for (int s = 16; s > 0; s >>= 1) {
            unsigned long long o = __shfl_xor_sync(0xffffffffu, k, s);
            if (o > k) k = o;
        }
        if (lane == 0) swmax[wid] = k;
        __syncthreads();
        if (threadIdx.x == 0) {
            unsigned long long bm2 = swmax[0];
            #pragma unroll
            for (int w = 1; w < TPB / 32; w++) if (swmax[w] > bm2) bm2 = swmax[w];
            sbest = bm2;
        }
        __syncthreads();
        if (key == sbest && lv[0] >= 0.0f) {
            atomicOr(&g_topk_mask[(size_t)b * L + li[0]], 1ull << j);
            #pragma unroll
            for (int t2 = 0; t2 < TOPK - 1; t2++) { lv[t2] = lv[t2 + 1]; li[t2] = li[t2 + 1]; }
            lv[TOPK - 1] = -1.0f; li[TOPK - 1] = 0x7fffffff;
        }
        __syncthreads();
    }
}

// ---------------- kernel B: resolve single assignment per anchor ----------------
__global__ __launch_bounds__(TPB) void assign_kernel(
    const float* __restrict__ pred_scores,
    const float* __restrict__ pred_bboxes,
    const float* __restrict__ anchors,
    const int*   __restrict__ gt_labels,
    const float* __restrict__ gt_bboxes,
    const float* __restrict__ pad_mask,
    int B, int L, int C, int n)
{
    int b = blockIdx.y;
    int i = blockIdx.x * blockDim.x + threadIdx.x;

    __shared__ float4 sgt[64];
    __shared__ float  spad[64];
    for (int j = threadIdx.x; j < n; j += blockDim.x) {
        sgt[j]  = ((const float4*)gt_bboxes)[(size_t)b * n + j];
        spad[j] = pad_mask[b * n + j];
    }
    __syncthreads();
    if (i >= L) return;

    float4 p = ((const float4*)pred_bboxes)[(size_t)b * L + i];
    float parea = (p.z - p.x) * (p.w - p.y);
    float2 a = ((const float2*)anchors)[i];
    unsigned long long tmask = g_topk_mask[(size_t)b * L + i];

    int cnt = 0, pos_j = -1; float pos_iou = 0.0f;
    float best_iou = -1.0f; int best_j = 0;

    for (int j = 0; j < n; j++) {
        float4 g = sgt[j];
        float iw = fmaxf(fminf(g.z, p.z) - fmaxf(g.x, p.x), 0.0f);
        float ih = fmaxf(fminf(g.w, p.w) - fmaxf(g.y, p.y), 0.0f);
        float inter = iw * ih;
        float garea = (g.z - g.x) * (g.w - g.y);
        float iou = inter / (garea + parea - inter + EPSV);
        if (iou > best_iou) { best_iou = iou; best_j = j; }   // first-argmax
        float d = fminf(fminf(a.x - g.x, a.y - g.y), fminf(g.z - a.x, g.w - a.y));
        bool ing = (d > EPSV);
        if (((tmask >> j) & 1ull) && ing && spad[j] > 0.0f) {
            cnt++; pos_j = j; pos_iou = iou;
        }
    }

    size_t idx = (size_t)b * L + i;
    if (cnt == 0) {
        g_assigned[idx] = -1;
        g_align_sel[idx] = 0.0f;
        return;
    }
    int aj; float iou;
    if (cnt == 1) { aj = pos_j; iou = pos_iou; }
    else          { aj = best_j; iou = best_iou; }   // mps>1 -> is_max_iou column

    int label = gt_labels[b * n + aj];
    float cls = pred_scores[idx * C + label];
    float i2 = iou * iou;
    float align = cls * (i2 * i2 * i2);

    g_assigned[idx] = aj;
    g_align_sel[idx] = align;
    atomicMax((int*)&g_max_metrics[b * n + aj], __float_as_int(align));
    atomicMax((int*)&g_max_ious[b * n + aj],   __float_as_int(iou));
}

// ---------------- kernel C1: per-anchor small outputs ----------------
__global__ __launch_bounds__(TPB) void output_small_kernel(
    const int*   __restrict__ gt_labels,
    const float* __restrict__ gt_bboxes,
    const int*   __restrict__ bg_ptr,     // may be null
    float* __restrict__ out,
    int B, int L, int C, int n, int K)
{
    size_t idx = (size_t)blockIdx.x * blockDim.x + threadIdx.x;
    size_t BL = (size_t)B * L;
    if (idx >= BL) return;
    int b = (int)(idx / L);

    int bg = bg_ptr ? *bg_ptr : 1;
    int aj = g_assigned[idx];
    int agi = (aj < 0) ? 0 : aj;
    int label = (aj < 0) ? bg : gt_labels[b * n + agi];

    float s = 0.0f;
    if (aj >= 0) {
        float mm = __int_as_float((int)g_max_metrics[b * n + aj]);
        float mi = __int_as_float((int)g_max_ious[b * n + aj]);
        s = g_align_sel[idx] / (mm + EPSV) * mi;
    }

    size_t off_lab  = 0;
    size_t off_box  = off_lab + BL;
    size_t off_pose = off_box + 4 * BL;
    size_t off_sc   = off_pose + BL * (size_t)(K * 3);
    size_t off_agi  = off_sc + BL * (size_t)C;

    out[off_lab + idx] = (float)label;

    float4 gb = ((const float4*)gt_bboxes)[(size_t)b * n + agi];
    ((float4*)(out + off_box))[idx] = gb;

    float* os = out + off_sc + idx * (size_t)C;
    int m = 0;
    for (int c = 0; c <= C; c++) {
        if (c == bg) continue;
        os[m] = (label == c) ? s : 0.0f;
        m++;
    }

    out[off_agi + idx] = (float)(agi + b * n);
}

// ---------------- kernel C2: coalesced pose gather-copy ----------------
__global__ __launch_bounds__(TPB) void output_pose_kernel(
    const float* __restrict__ gt_poses,
    float* __restrict__ out,
    int B, int L, int n, int K3)
{
    size_t BL = (size_t)B * L;
    size_t total = BL * (size_t)K3;
    size_t e = (size_t)blockIdx.x * blockDim.x + threadIdx.x;
    if (e >= total) return;

    size_t idx = e / (size_t)K3;          // anchor
    int t = (int)(e - idx * (size_t)K3);  // pose element
    int b = (int)(idx / L);

    int aj = g_assigned[idx];
    int agi = (aj < 0) ? 0 : aj;

    size_t off_pose = BL * 5;             // after labels (BL) + boxes (4*BL)
    out[off_pose + e] = gt_poses[((size_t)b * n + agi) * (size_t)K3 + t];
}

// ---------------- launcher ----------------
extern "C" void kernel_launch(void* const* d_in, const int* in_sizes, int n_in,
                              void* d_out, int out_size)
{
    const float* pred_scores = (const float*)d_in[0];
    const float* pred_bboxes = (const float*)d_in[1];
    // d_in[2] pred_poses: unused by the reference
    const float* anchors     = (const float*)d_in[3];
    const int*   gt_labels   = (const int*)d_in[4];
    const float* gt_bboxes   = (const float*)d_in[5];
    const float* gt_poses    = (const float*)d_in[6];
    const float* pad_mask    = (const float*)d_in[7];
    const int*   bg_ptr      = (n_in > 8) ? (const int*)d_in[8] : nullptr;

    int L = in_sizes[3] / 2;
    int B = in_sizes[1] / (4 * L);
    int C = in_sizes[0] / (B * L);
    int K = in_sizes[2] / (B * L * 3);
    int n = in_sizes[5] / (B * 4);

    int BL = B * L;
    int Bn = B * n;

    init_kernel<<<(BL + TPB - 1) / TPB, TPB>>>(BL, Bn);

    dim3 gridA((L + TPB - 1) / TPB, B);
    cand_kernel<<<gridA, TPB>>>(pred_scores, pred_bboxes, anchors,
                                gt_labels, gt_bboxes, pad_mask, B, L, C, n);

    select_kernel<<<(Bn + (TPB / 32) - 1) / (TPB / 32), TPB>>>(pad_mask, B, L, n);

    topk_fallback_kernel<<<Bn, TPB>>>(pred_scores, pred_bboxes, anchors,
                                      gt_labels, gt_bboxes, B, L, C, n);

    assign_kernel<<<gridA, TPB>>>(pred_scores, pred_bboxes, anchors,
                                  gt_labels, gt_bboxes, pad_mask, B, L, C, n);

    output_small_kernel<<<(BL + TPB - 1) / TPB, TPB>>>(gt_labels, gt_bboxes,
                                                       bg_ptr, (float*)d_out,
                                                       B, L, C, n, K);

    size_t pose_total = (size_t)BL * (size_t)(K * 3);
    int pose_blocks = (int)((pose_total + TPB - 1) / TPB);
    output_pose_kernel<<<pose_blocks, TPB>>>(gt_poses, (float*)d_out,
                                             B, L, n, K * 3);
}

// round 4
// speedup vs baseline: 2.6590x; 1.4393x over previous
#include <cuda_runtime.h>
#include <cuda_bf16.h>
#include <cstdint>

#define EPSV 1e-9f
#define TOPK 13
#define MAXBL (32 * 8400)
#define MAXBN 2048
#define CAP 256
#define TPB 256

// ---------------- device scratch (no allocation allowed) ----------------
__device__ unsigned long long g_topk_mask[MAXBL];   // bit j set => anchor i in topk of gt j
__device__ int g_assigned[MAXBL];                   // final single assigned gt (-1 if none)
__device__ float g_align_sel[MAXBL];                // align value at assigned gt
__device__ unsigned int g_max_metrics[MAXBN];       // float bits, per (b, j)
__device__ unsigned int g_max_ious[MAXBN];          // float bits, per (b, j)
__device__ unsigned long long g_cand[(size_t)MAXBN * CAP];  // packed (val, idx) keys
__device__ int g_cnt[MAXBN];                        // candidate count per row

// ---------------- tiny init (per-GT-row arrays only) ----------------
__global__ void init_kernel(int Bn) {
    int i = blockIdx.x * blockDim.x + threadIdx.x;
    if (i < Bn) {
        g_max_metrics[i] = 0u; g_max_ious[i] = 0u;
        g_cnt[i] = 0;
    }
}

// ---------------- kernel A1: candidate compaction (anchor-parallel) ----------------
// also zeroes g_topk_mask (each thread owns its anchor's slot)
__global__ __launch_bounds__(TPB) void cand_kernel(
    const float* __restrict__ pred_scores,   // (B,L,C)
    const float* __restrict__ pred_bboxes,   // (B,L,4)
    const float* __restrict__ anchors,       // (L,2)
    const int*   __restrict__ gt_labels,     // (B,n,1)
    const float* __restrict__ gt_bboxes,     // (B,n,4)
    const float* __restrict__ pad_mask,      // (B,n,1)
    int B, int L, int C, int n)
{
    int b = blockIdx.y;
    int i = blockIdx.x * blockDim.x + threadIdx.x;

    __shared__ float4 sgt[64];
    __shared__ float  spad[64];
    __shared__ int    slab[64];
    for (int j = threadIdx.x; j < n; j += blockDim.x) {
        sgt[j]  = ((const float4*)gt_bboxes)[(size_t)b * n + j];
        spad[j] = pad_mask[b * n + j];
        slab[j] = gt_labels[b * n + j];
    }
    __syncthreads();
    if (i >= L) return;

    g_topk_mask[(size_t)b * L + i] = 0ull;   // owned slot; set later only by select

    float4 p = ((const float4*)pred_bboxes)[(size_t)b * L + i];
    float parea = (p.z - p.x) * (p.w - p.y);
    float2 a = ((const float2*)anchors)[i];
    const float* psb = pred_scores + ((size_t)b * L + i) * C;

    unsigned int enc_i = 0x7fffffffu - (unsigned int)i;

    for (int j = 0; j < n; j++) {
        if (spad[j] <= 0.0f) continue;
        float4 g = sgt[j];
        float d = fminf(fminf(a.x - g.x, a.y - g.y), fminf(g.z - a.x, g.w - a.y));
        if (d <= EPSV) continue;                      // not in gts -> metric 0
        float iw = fmaxf(fminf(g.z, p.z) - fmaxf(g.x, p.x), 0.0f);
        float ih = fmaxf(fminf(g.w, p.w) - fmaxf(g.y, p.y), 0.0f);
        float inter = iw * ih;
        float garea = (g.z - g.x) * (g.w - g.y);
        float iou = inter / (garea + parea - inter + EPSV);
        float cls = psb[slab[j]];
        float i2 = iou * iou;
        float v = cls * (i2 * i2 * i2);
        if (v > 0.0f) {
            int row = b * n + j;
            int pos = atomicAdd(&g_cnt[row], 1);
            if (pos < CAP) {
                unsigned long long key =
                    ((unsigned long long)__float_as_uint(v) << 32) | enc_i;
                g_cand[(size_t)row * CAP + pos] = key;
            }
        }
    }
}

// ---------------- kernel A2: per-row top-13 select (one warp per (b,j)) ----------------
// includes inline warp full-L rescan for (essentially never taken) overflow rows
__global__ __launch_bounds__(TPB) void select_kernel(
    const float* __restrict__ pred_scores,
    const float* __restrict__ pred_bboxes,
    const float* __restrict__ anchors,
    const int*   __restrict__ gt_labels,
    const float* __restrict__ gt_bboxes,
    const float* __restrict__ pad_mask,
    int B, int L, int C, int n)
{
    int wid  = threadIdx.x >> 5;
    int lane = threadIdx.x & 31;
    int r = blockIdx.x * (TPB / 32) + wid;
    __shared__ unsigned int bm[TPB / 32][20];   // 640-bit index bitmap per warp
    if (r >= B * n) return;
    if (pad_mask[r] <= 0.0f) return;            // padded row -> no topk bits

    int b = r / n;
    int j = r - b * n;
    unsigned long long jbit = 1ull << j;
    int c = g_cnt[r];

    if (c <= CAP) {
        const unsigned long long* buf = g_cand + (size_t)r * CAP;

        unsigned long long ck[CAP / 32];
        #pragma unroll
        for (int s = 0; s < CAP / 32; s++) {
            int idx = s * 32 + lane;
            ck[s] = (idx < c) ? buf[idx] : 0ull;
        }

        // bitmap of candidate indices < 640 (for exact zero-metric tie fill)
        for (int w = lane; w < 20; w += 32) bm[wid][w] = 0u;
        __syncwarp();
        #pragma unroll
        for (int s = 0; s < CAP / 32; s++) {
            if (ck[s]) {
                unsigned int ai = 0x7fffffffu - (unsigned int)(ck[s] & 0xffffffffu);
                if (ai < 640u) atomicOr(&bm[wid][ai >> 5], 1u << (ai & 31u));
            }
        }
        __syncwarp();

        // up-to-13 rounds of warp argmax (value desc, index asc) over positives
        int p = 0;
        for (int t = 0; t < TOPK; t++) {
            unsigned long long m = 0ull;
            #pragma unroll
            for (int s = 0; s < CAP / 32; s++) if (ck[s] > m) m = ck[s];
            #pragma unroll
            for (int sh = 16; sh > 0; sh >>= 1) {
                unsigned long long o = __shfl_xor_sync(0xffffffffu, m, sh);
                if (o > m) m = o;
            }
            if (m == 0ull) break;       // positives exhausted
            p++;
            #pragma unroll
            for (int s = 0; s < CAP / 32; s++) {
                if (ck[s] == m) {       // keys unique (index embedded)
                    ck[s] = 0ull;
                    unsigned int ai = 0x7fffffffu - (unsigned int)(m & 0xffffffffu);
                    atomicOr(&g_topk_mask[(size_t)b * L + ai], jbit);
                }
            }
        }

        // zero-metric tie fill: smallest indices with metric == 0
        if (lane == 0) {
            int rem = TOPK - p;
            int i = 0;
            while (rem > 0 && i < 640) {
                if (!((bm[wid][i >> 5] >> (i & 31u)) & 1u)) {
                    atomicOr(&g_topk_mask[(size_t)b * L + i], jbit);
                    rem--;
                }
                i++;
            }
        }
        return;
    }

    // ---- overflow fallback: warp-wide full-L rescan (c > CAP > 13 positives,
    // so no zero-tie fill needed) ----
    const float4 g = __ldg((const float4*)gt_bboxes + r);
    const float garea = (g.z - g.x) * (g.w - g.y);
    const int label = gt_labels[r];
    const float4* pb = (const float4*)pred_bboxes + (size_t)b * L;
    const float*  ps = pred_scores + (size_t)b * L * C;
    const float2* ap = (const float2*)anchors;

    float lv[TOPK]; int li[TOPK];
    #pragma unroll
    for (int t = 0; t < TOPK; t++) { lv[t] = -1.0f; li[t] = 0x7fffffff; }

    for (int i = lane; i < L; i += 32) {
        float4 p = pb[i];
        float iw = fmaxf(fminf(g.z, p.z) - fmaxf(g.x, p.x), 0.0f);
        float ih = fmaxf(fminf(g.w, p.w) - fmaxf(g.y, p.y), 0.0f);
        float inter = iw * ih;
        float parea = (p.z - p.x) * (p.w - p.y);
        float iou = inter / (garea + parea - inter + EPSV);
        float cls = ps[(size_t)i * C + label];
        float i2 = iou * iou;
        float align = cls * (i2 * i2 * i2);
        float2 a = ap[i];
        float d = fminf(fminf(a.x - g.x, a.y - g.y), fminf(g.z - a.x, g.w - a.y));
        float v = (d > EPSV) ? align : 0.0f;
        if (v > lv[TOPK - 1]) {
            lv[TOPK - 1] = v; li[TOPK - 1] = i;
            #pragma unroll
            for (int t = TOPK - 1; t > 0; t--) {
                if (lv[t] > lv[t - 1]) {
                    float tv = lv[t]; lv[t] = lv[t - 1]; lv[t - 1] = tv;
                    int   ti = li[t]; li[t] = li[t - 1]; li[t - 1] = ti;
                }
            }
        }
    }

    for (int t = 0; t < TOPK; t++) {
        unsigned long long key =
            ((unsigned long long)__float_as_uint(fmaxf(lv[0], 0.0f)) << 32) |
            (unsigned int)(0x7fffffff - li[0]);
        unsigned long long k = key;
        #pragma unroll
        for (int s = 16; s > 0; s >>= 1) {
            unsigned long long o = __shfl_xor_sync(0xffffffffu, k, s);
            if (o > k) k = o;
        }
        if (key == k && lv[0] >= 0.0f) {   // this lane holds the winner
            atomicOr(&g_topk_mask[(size_t)b * L + li[0]], jbit);
            #pragma unroll
            for (int t2 = 0; t2 < TOPK - 1; t2++) { lv[t2] = lv[t2 + 1]; li[t2] = li[t2 + 1]; }
            lv[TOPK - 1] = -1.0f; li[TOPK - 1] = 0x7fffffff;
        }
        __syncwarp();
    }
}

// ---------------- kernel B: resolve single assignment per anchor ----------------
__global__ __launch_bounds__(TPB) void assign_kernel(
    const float* __restrict__ pred_scores,
    const float* __restrict__ pred_bboxes,
    const float* __restrict__ anchors,
    const int*   __restrict__ gt_labels,
    const float* __restrict__ gt_bboxes,
    const float* __restrict__ pad_mask,
    int B, int L, int C, int n)
{
    int b = blockIdx.y;
    int i = blockIdx.x * blockDim.x + threadIdx.x;

    __shared__ float4 sgt[64];
    __shared__ float  spad[64];
    for (int j = threadIdx.x; j < n; j += blockDim.x) {
        sgt[j]  = ((const float4*)gt_bboxes)[(size_t)b * n + j];
        spad[j] = pad_mask[b * n + j];
    }
    __syncthreads();
    if (i >= L) return;

    float4 p = ((const float4*)pred_bboxes)[(size_t)b * L + i];
    float parea = (p.z - p.x) * (p.w - p.y);
    float2 a = ((const float2*)anchors)[i];
    unsigned long long tmask = g_topk_mask[(size_t)b * L + i];

    int cnt = 0, pos_j = -1; float pos_iou = 0.0f;
    float best_iou = -1.0f; int best_j = 0;

    for (int j = 0; j < n; j++) {
        float4 g = sgt[j];
        float iw = fmaxf(fminf(g.z, p.z) - fmaxf(g.x, p.x), 0.0f);
        float ih = fmaxf(fminf(g.w, p.w) - fmaxf(g.y, p.y), 0.0f);
        float inter = iw * ih;
        float garea = (g.z - g.x) * (g.w - g.y);
        float iou = inter / (garea + parea - inter + EPSV);
        if (iou > best_iou) { best_iou = iou; best_j = j; }   // first-argmax
        float d = fminf(fminf(a.x - g.x, a.y - g.y), fminf(g.z - a.x, g.w - a.y));
        bool ing = (d > EPSV);
        if (((tmask >> j) & 1ull) && ing && spad[j] > 0.0f) {
            cnt++; pos_j = j; pos_iou = iou;
        }
    }

    size_t idx = (size_t)b * L + i;
    if (cnt == 0) {
        g_assigned[idx] = -1;
        g_align_sel[idx] = 0.0f;
        return;
    }
    int aj; float iou;
    if (cnt == 1) { aj = pos_j; iou = pos_iou; }
    else          { aj = best_j; iou = best_iou; }   // mps>1 -> is_max_iou column

    int label = gt_labels[b * n + aj];
    float cls = pred_scores[idx * C + label];
    float i2 = iou * iou;
    float align = cls * (i2 * i2 * i2);

    g_assigned[idx] = aj;
    g_align_sel[idx] = align;
    atomicMax((int*)&g_max_metrics[b * n + aj], __float_as_int(align));
    atomicMax((int*)&g_max_ious[b * n + aj],   __float_as_int(iou));
}

// ---------------- kernel C: fused outputs (scalars + warp-cooperative pose copy) ----------------
__global__ __launch_bounds__(TPB) void output_fused_kernel(
    const int*   __restrict__ gt_labels,
    const float* __restrict__ gt_bboxes,
    const float* __restrict__ gt_poses,
    const int*   __restrict__ bg_ptr,     // may be null
    float* __restrict__ out,
    int B, int L, int C, int n, int K)
{
    size_t BL = (size_t)B * L;
    int lane = threadIdx.x & 31;
    size_t base = ((size_t)blockIdx.x * blockDim.x + (threadIdx.x & ~31)); // warp's first anchor
    size_t idx = base + lane;

    int K3 = K * 3;
    size_t off_lab  = 0;
    size_t off_box  = off_lab + BL;
    size_t off_pose = off_box + 4 * BL;
    size_t off_sc   = off_pose + BL * (size_t)K3;
    size_t off_agi  = off_sc + BL * (size_t)C;

    int bg = bg_ptr ? *bg_ptr : 1;
    int grow = 0;   // gt row for pose gather (b*n + agi)

    if (idx < BL) {
        int b = (int)(idx / L);
        int aj = g_assigned[idx];
        int agi = (aj < 0) ? 0 : aj;
        grow = b * n + agi;
        int label = (aj < 0) ? bg : gt_labels[grow];

        float s = 0.0f;
        if (aj >= 0) {
            float mm = __int_as_float((int)g_max_metrics[grow]);
            float mi = __int_as_float((int)g_max_ious[grow]);
            s = g_align_sel[idx] / (mm + EPSV) * mi;
        }

        out[off_lab + idx] = (float)label;
        ((float4*)(out + off_box))[idx] = ((const float4*)gt_bboxes)[grow];

        float* os = out + off_sc + idx * (size_t)C;
        int m = 0;
        for (int c = 0; c <= C; c++) {
            if (c == bg) continue;
            os[m] = (label == c) ? s : 0.0f;
            m++;
        }
        out[off_agi + idx] = (float)grow;
    }

    // warp-cooperative pose copy: 51 consecutive floats per anchor
    #pragma unroll 1
    for (int m = 0; m < 32; m++) {
        size_t aidx = base + (size_t)m;
        if (aidx >= BL) break;
        int gr = __shfl_sync(0xffffffffu, grow, m);
        const float* gp = gt_poses + (size_t)gr * (size_t)K3;
        float* op = out + off_pose + aidx * (size_t)K3;
        for (int t = lane; t < K3; t += 32) op[t] = gp[t];
    }
}

// ---------------- launcher ----------------
extern "C" void kernel_launch(void* const* d_in, const int* in_sizes, int n_in,
                              void* d_out, int out_size)
{
    const float* pred_scores = (const float*)d_in[0];
    const float* pred_bboxes = (const float*)d_in[1];
    // d_in[2] pred_poses: unused by the reference
    const float* anchors     = (const float*)d_in[3];
    const int*   gt_labels   = (const int*)d_in[4];
    const float* gt_bboxes   = (const float*)d_in[5];
    const float* gt_poses    = (const float*)d_in[6];
    const float* pad_mask    = (const float*)d_in[7];
    const int*   bg_ptr      = (n_in > 8) ? (const int*)d_in[8] : nullptr;

    int L = in_sizes[3] / 2;
    int B = in_sizes[1] / (4 * L);
    int C = in_sizes[0] / (B * L);
    int K = in_sizes[2] / (B * L * 3);
    int n = in_sizes[5] / (B * 4);

    int BL = B * L;
    int Bn = B * n;

    init_kernel<<<(Bn + TPB - 1) / TPB, TPB>>>(Bn);

    dim3 gridA((L + TPB - 1) / TPB, B);
    cand_kernel<<<gridA, TPB>>>(pred_scores, pred_bboxes, anchors,
                                gt_labels, gt_bboxes, pad_mask, B, L, C, n);

    select_kernel<<<(Bn + (TPB / 32) - 1) / (TPB / 32), TPB>>>(
        pred_scores, pred_bboxes, anchors, gt_labels, gt_bboxes, pad_mask,
        B, L, C, n);

    assign_kernel<<<gridA, TPB>>>(pred_scores, pred_bboxes, anchors,
                                  gt_labels, gt_bboxes, pad_mask, B, L, C, n);

    output_fused_kernel<<<(BL + TPB - 1) / TPB, TPB>>>(gt_labels, gt_bboxes,
                                                       gt_poses, bg_ptr,
                                                       (float*)d_out,
                                                       B, L, C, n, K);
}

// round 5
// speedup vs baseline: 3.2425x; 1.2195x over previous
#include <cuda_runtime.h>
#include <cuda_bf16.h>
#include <cstdint>

#define EPSV 1e-9f
#define TOPK 13
#define MAXBL (32 * 8400)
#define MAXBN 2048
#define CAP 256
#define TPB 256

// ---------------- device scratch (no allocation allowed) ----------------
__device__ unsigned long long g_topk_mask[MAXBL];   // bit j set => anchor i in topk of gt j
__device__ int g_assigned[MAXBL];                   // final single assigned gt (-1 if none)
__device__ float g_align_sel[MAXBL];                // align value at assigned gt
__device__ unsigned int g_max_metrics[MAXBN];       // float bits, per (b, j)
__device__ unsigned int g_max_ious[MAXBN];          // float bits, per (b, j)
__device__ unsigned long long g_cand[(size_t)MAXBN * CAP];  // packed (val, idx) keys
__device__ int g_cnt[MAXBN];                        // candidate count per row

// ---------------- tiny init (per-GT-row arrays only) ----------------
__global__ void init_kernel(int Bn) {
    int i = blockIdx.x * blockDim.x + threadIdx.x;
    if (i < Bn) {
        g_max_metrics[i] = 0u; g_max_ious[i] = 0u;
        g_cnt[i] = 0;
    }
}

// ---------------- kernel A1: candidate compaction (anchor-parallel) ----------------
// also zeroes g_topk_mask (each thread owns its anchor's slot)
__global__ __launch_bounds__(TPB) void cand_kernel(
    const float* __restrict__ pred_scores,   // (B,L,C)
    const float* __restrict__ pred_bboxes,   // (B,L,4)
    const float* __restrict__ anchors,       // (L,2)
    const int*   __restrict__ gt_labels,     // (B,n,1)
    const float* __restrict__ gt_bboxes,     // (B,n,4)
    const float* __restrict__ pad_mask,      // (B,n,1)
    int B, int L, int C, int n)
{
    int b = blockIdx.y;
    int i = blockIdx.x * blockDim.x + threadIdx.x;

    // compact non-padded GTs
    __shared__ float4 sgt[64];
    __shared__ int    slab[64];   // label
    __shared__ int    sj[64];     // original j
    __shared__ int    snum;
    if (threadIdx.x == 0) {
        int m = 0;
        for (int j = 0; j < n; j++) {
            if (pad_mask[b * n + j] > 0.0f) {
                sgt[m]  = ((const float4*)gt_bboxes)[(size_t)b * n + j];
                slab[m] = gt_labels[b * n + j];
                sj[m]   = j;
                m++;
            }
        }
        snum = m;
    }
    __syncthreads();
    if (i >= L) return;

    g_topk_mask[(size_t)b * L + i] = 0ull;   // owned slot; set later only by select

    const int nn = snum;
    float4 p = ((const float4*)pred_bboxes)[(size_t)b * L + i];
    float parea = (p.z - p.x) * (p.w - p.y);
    float2 a = ((const float2*)anchors)[i];
    const float* psb = pred_scores + ((size_t)b * L + i) * C;

    unsigned int enc_i = 0x7fffffffu - (unsigned int)i;

    for (int m = 0; m < nn; m++) {
        float4 g = sgt[m];
        // exact reference in-gts test: all four deltas > EPS
        bool ing = (a.x - g.x > EPSV) && (a.y - g.y > EPSV) &&
                   (g.z - a.x > EPSV) && (g.w - a.y > EPSV);
        if (!ing) continue;
        float iw = fmaxf(fminf(g.z, p.z) - fmaxf(g.x, p.x), 0.0f);
        float ih = fmaxf(fminf(g.w, p.w) - fmaxf(g.y, p.y), 0.0f);
        float inter = iw * ih;
        float garea = (g.z - g.x) * (g.w - g.y);
        float iou = inter / (garea + parea - inter + EPSV);
        float cls = psb[slab[m]];
        float i2 = iou * iou;
        float v = cls * (i2 * i2 * i2);
        if (v > 0.0f) {
            int row = b * n + sj[m];
            int pos = atomicAdd(&g_cnt[row], 1);
            if (pos < CAP) {
                unsigned long long key =
                    ((unsigned long long)__float_as_uint(v) << 32) | enc_i;
                g_cand[(size_t)row * CAP + pos] = key;
            }
        }
    }
}

// ---------------- kernel A2: per-row top-13 select (one warp per (b,j)) ----------------
// includes inline warp full-L rescan for (essentially never taken) overflow rows
__global__ __launch_bounds__(TPB) void select_kernel(
    const float* __restrict__ pred_scores,
    const float* __restrict__ pred_bboxes,
    const float* __restrict__ anchors,
    const int*   __restrict__ gt_labels,
    const float* __restrict__ gt_bboxes,
    const float* __restrict__ pad_mask,
    int B, int L, int C, int n)
{
    int wid  = threadIdx.x >> 5;
    int lane = threadIdx.x & 31;
    int r = blockIdx.x * (TPB / 32) + wid;
    __shared__ unsigned int bm[TPB / 32][20];   // 640-bit index bitmap per warp
    if (r >= B * n) return;
    if (pad_mask[r] <= 0.0f) return;            // padded row -> no topk bits

    int b = r / n;
    int j = r - b * n;
    unsigned long long jbit = 1ull << j;
    int c = g_cnt[r];

    if (c <= CAP) {
        const unsigned long long* buf = g_cand + (size_t)r * CAP;

        unsigned long long ck[CAP / 32];
        #pragma unroll
        for (int s = 0; s < CAP / 32; s++) {
            int idx = s * 32 + lane;
            ck[s] = (idx < c) ? buf[idx] : 0ull;
        }

        // bitmap of candidate indices < 640 (for exact zero-metric tie fill)
        for (int w = lane; w < 20; w += 32) bm[wid][w] = 0u;
        __syncwarp();
        #pragma unroll
        for (int s = 0; s < CAP / 32; s++) {
            if (ck[s]) {
                unsigned int ai = 0x7fffffffu - (unsigned int)(ck[s] & 0xffffffffu);
                if (ai < 640u) atomicOr(&bm[wid][ai >> 5], 1u << (ai & 31u));
            }
        }
        __syncwarp();

        // up-to-13 rounds of warp argmax (value desc, index asc) over positives
        int p = 0;
        for (int t = 0; t < TOPK; t++) {
            unsigned long long m = 0ull;
            #pragma unroll
            for (int s = 0; s < CAP / 32; s++) if (ck[s] > m) m = ck[s];
            #pragma unroll
            for (int sh = 16; sh > 0; sh >>= 1) {
                unsigned long long o = __shfl_xor_sync(0xffffffffu, m, sh);
                if (o > m) m = o;
            }
            if (m == 0ull) break;       // positives exhausted
            p++;
            #pragma unroll
            for (int s = 0; s < CAP / 32; s++) {
                if (ck[s] == m) {       // keys unique (index embedded)
                    ck[s] = 0ull;
                    unsigned int ai = 0x7fffffffu - (unsigned int)(m & 0xffffffffu);
                    atomicOr(&g_topk_mask[(size_t)b * L + ai], jbit);
                }
            }
        }

        // zero-metric tie fill: smallest indices with metric == 0
        if (lane == 0) {
            int rem = TOPK - p;
            int i = 0;
            while (rem > 0 && i < 640) {
                if (!((bm[wid][i >> 5] >> (i & 31u)) & 1u)) {
                    atomicOr(&g_topk_mask[(size_t)b * L + i], jbit);
                    rem--;
                }
                i++;
            }
        }
        return;
    }

    // ---- overflow fallback: warp-wide full-L rescan (c > CAP > 13 positives,
    // so no zero-tie fill needed) ----
    const float4 g = __ldg((const float4*)gt_bboxes + r);
    const float garea = (g.z - g.x) * (g.w - g.y);
    const int label = gt_labels[r];
    const float4* pb = (const float4*)pred_bboxes + (size_t)b * L;
    const float*  ps = pred_scores + (size_t)b * L * C;
    const float2* ap = (const float2*)anchors;

    float lv[TOPK]; int li[TOPK];
    #pragma unroll
    for (int t = 0; t < TOPK; t++) { lv[t] = -1.0f; li[t] = 0x7fffffff; }

    for (int i = lane; i < L; i += 32) {
        float4 p = pb[i];
        float iw = fmaxf(fminf(g.z, p.z) - fmaxf(g.x, p.x), 0.0f);
        float ih = fmaxf(fminf(g.w, p.w) - fmaxf(g.y, p.y), 0.0f);
        float inter = iw * ih;
        float parea = (p.z - p.x) * (p.w - p.y);
        float iou = inter / (garea + parea - inter + EPSV);
        float cls = ps[(size_t)i * C + label];
        float i2 = iou * iou;
        float align = cls * (i2 * i2 * i2);
        float2 a = ap[i];
        float d = fminf(fminf(a.x - g.x, a.y - g.y), fminf(g.z - a.x, g.w - a.y));
        float v = (d > EPSV) ? align : 0.0f;
        if (v > lv[TOPK - 1]) {
            lv[TOPK - 1] = v; li[TOPK - 1] = i;
            #pragma unroll
            for (int t = TOPK - 1; t > 0; t--) {
                if (lv[t] > lv[t - 1]) {
                    float tv = lv[t]; lv[t] = lv[t - 1]; lv[t - 1] = tv;
                    int   ti = li[t]; li[t] = li[t - 1]; li[t - 1] = ti;
                }
            }
        }
    }

    for (int t = 0; t < TOPK; t++) {
        unsigned long long key =
            ((unsigned long long)__float_as_uint(fmaxf(lv[0], 0.0f)) << 32) |
            (unsigned int)(0x7fffffff - li[0]);
        unsigned long long k = key;
        #pragma unroll
        for (int s = 16; s > 0; s >>= 1) {
            unsigned long long o = __shfl_xor_sync(0xffffffffu, k, s);
            if (o > k) k = o;
        }
        if (key == k && lv[0] >= 0.0f) {   // this lane holds the winner
            atomicOr(&g_topk_mask[(size_t)b * L + li[0]], jbit);
            #pragma unroll
            for (int t2 = 0; t2 < TOPK - 1; t2++) { lv[t2] = lv[t2 + 1]; li[t2] = li[t2 + 1]; }
            lv[TOPK - 1] = -1.0f; li[TOPK - 1] = 0x7fffffff;
        }
        __syncwarp();
    }
}

// ---------------- kernel B: sparse assignment (iterate set bits only) ----------------
__global__ __launch_bounds__(TPB) void assign_sparse_kernel(
    const float* __restrict__ pred_scores,
    const float* __restrict__ pred_bboxes,
    const float* __restrict__ anchors,
    const int*   __restrict__ gt_labels,
    const float* __restrict__ gt_bboxes,
    const float* __restrict__ pad_mask,
    int B, int L, int C, int n)
{
    size_t idx = (size_t)blockIdx.x * blockDim.x + threadIdx.x;
    size_t BL = (size_t)B * L;
    if (idx >= BL) return;

    unsigned long long tmask = g_topk_mask[idx];
    if (tmask == 0ull) {                 // ~92% of anchors: no topk claim at all
        g_assigned[idx] = -1;
        g_align_sel[idx] = 0.0f;
        return;
    }

    int b = (int)(idx / L);
    int i = (int)(idx - (size_t)b * L);

    float4 p = ((const float4*)pred_bboxes)[idx];
    float parea = (p.z - p.x) * (p.w - p.y);
    float2 a = ((const float2*)anchors)[i];
    const float4* gtb = (const float4*)gt_bboxes + (size_t)b * n;
    const float*  pad = pad_mask + (size_t)b * n;

    int cnt = 0, pos_j = -1; float pos_iou = 0.0f;

    unsigned long long m = tmask;
    while (m) {
        int j = __ffsll((long long)m) - 1;
        m &= m - 1;
        float4 g = gtb[j];
        bool ing = (a.x - g.x > EPSV) && (a.y - g.y > EPSV) &&
                   (g.z - a.x > EPSV) && (g.w - a.y > EPSV);
        if (ing && pad[j] > 0.0f) {
            float iw = fmaxf(fminf(g.z, p.z) - fmaxf(g.x, p.x), 0.0f);
            float ih = fmaxf(fminf(g.w, p.w) - fmaxf(g.y, p.y), 0.0f);
            float inter = iw * ih;
            float garea = (g.z - g.x) * (g.w - g.y);
            float iou = inter / (garea + parea - inter + EPSV);
            cnt++; pos_j = j; pos_iou = iou;
        }
    }

    if (cnt == 0) {                      // tie-fill bits only -> background
        g_assigned[idx] = -1;
        g_align_sel[idx] = 0.0f;
        return;
    }

    int aj; float iou;
    if (cnt == 1) {
        aj = pos_j; iou = pos_iou;
    } else {
        // mps > 1 -> replace with is_max_iou: first argmax of iou over ALL n GTs
        float best_iou = -1.0f; int best_j = 0;
        for (int j = 0; j < n; j++) {
            float4 g = gtb[j];
            float iw = fmaxf(fminf(g.z, p.z) - fmaxf(g.x, p.x), 0.0f);
            float ih = fmaxf(fminf(g.w, p.w) - fmaxf(g.y, p.y), 0.0f);
            float inter = iw * ih;
            float garea = (g.z - g.x) * (g.w - g.y);
            float v = inter / (garea + parea - inter + EPSV);
            if (v > best_iou) { best_iou = v; best_j = j; }
        }
        aj = best_j; iou = best_iou;
    }

    int label = gt_labels[b * n + aj];
    float cls = pred_scores[idx * C + label];
    float i2 = iou * iou;
    float align = cls * (i2 * i2 * i2);

    g_assigned[idx] = aj;
    g_align_sel[idx] = align;
    atomicMax((int*)&g_max_metrics[b * n + aj], __float_as_int(align));
    atomicMax((int*)&g_max_ious[b * n + aj],   __float_as_int(iou));
}

// ---------------- kernel C: fused outputs (scalars + warp-cooperative pose copy) ----------------
__global__ __launch_bounds__(TPB) void output_fused_kernel(
    const int*   __restrict__ gt_labels,
    const float* __restrict__ gt_bboxes,
    const float* __restrict__ gt_poses,
    const int*   __restrict__ bg_ptr,     // may be null
    float* __restrict__ out,
    int B, int L, int C, int n, int K)
{
    size_t BL = (size_t)B * L;
    int lane = threadIdx.x & 31;
    size_t base = ((size_t)blockIdx.x * blockDim.x + (threadIdx.x & ~31)); // warp's first anchor
    size_t idx = base + lane;

    int K3 = K * 3;
    size_t off_lab  = 0;
    size_t off_box  = off_lab + BL;
    size_t off_pose = off_box + 4 * BL;
    size_t off_sc   = off_pose + BL * (size_t)K3;
    size_t off_agi  = off_sc + BL * (size_t)C;

    int bg = bg_ptr ? *bg_ptr : 1;
    int grow = 0;   // gt row for pose gather (b*n + agi)

    if (idx < BL) {
        int b = (int)(idx / L);
        int aj = g_assigned[idx];
        int agi = (aj < 0) ? 0 : aj;
        grow = b * n + agi;
        int label = (aj < 0) ? bg : gt_labels[grow];

        float s = 0.0f;
        if (aj >= 0) {
            float mm = __int_as_float((int)g_max_metrics[grow]);
            float mi = __int_as_float((int)g_max_ious[grow]);
            s = g_align_sel[idx] / (mm + EPSV) * mi;
        }

        out[off_lab + idx] = (float)label;
        ((float4*)(out + off_box))[idx] = ((const float4*)gt_bboxes)[grow];

        float* os = out + off_sc + idx * (size_t)C;
        int m = 0;
        for (int c = 0; c <= C; c++) {
            if (c == bg) continue;
            os[m] = (label == c) ? s : 0.0f;
            m++;
        }
        out[off_agi + idx] = (float)grow;
    }

    // warp-cooperative pose copy: 51 consecutive floats per anchor
    #pragma unroll 1
    for (int m = 0; m < 32; m++) {
        size_t aidx = base + (size_t)m;
        if (aidx >= BL) break;
        int gr = __shfl_sync(0xffffffffu, grow, m);
        const float* gp = gt_poses + (size_t)gr * (size_t)K3;
        float* op = out + off_pose + aidx * (size_t)K3;
        for (int t = lane; t < K3; t += 32) op[t] = gp[t];
    }
}

// ---------------- launcher ----------------
extern "C" void kernel_launch(void* const* d_in, const int* in_sizes, int n_in,
                              void* d_out, int out_size)
{
    const float* pred_scores = (const float*)d_in[0];
    const float* pred_bboxes = (const float*)d_in[1];
    // d_in[2] pred_poses: unused by the reference
    const float* anchors     = (const float*)d_in[3];
    const int*   gt_labels   = (const int*)d_in[4];
    const float* gt_bboxes   = (const float*)d_in[5];
    const float* gt_poses    = (const float*)d_in[6];
    const float* pad_mask    = (const float*)d_in[7];
    const int*   bg_ptr      = (n_in > 8) ? (const int*)d_in[8] : nullptr;

    int L = in_sizes[3] / 2;
    int B = in_sizes[1] / (4 * L);
    int C = in_sizes[0] / (B * L);
    int K = in_sizes[2] / (B * L * 3);
    int n = in_sizes[5] / (B * 4);

    int BL = B * L;
    int Bn = B * n;

    init_kernel<<<(Bn + TPB - 1) / TPB, TPB>>>(Bn);

    dim3 gridA((L + TPB - 1) / TPB, B);
    cand_kernel<<<gridA, TPB>>>(pred_scores, pred_bboxes, anchors,
                                gt_labels, gt_bboxes, pad_mask, B, L, C, n);

    select_kernel<<<(Bn + (TPB / 32) - 1) / (TPB / 32), TPB>>>(
        pred_scores, pred_bboxes, anchors, gt_labels, gt_bboxes, pad_mask,
        B, L, C, n);

    assign_sparse_kernel<<<(BL + TPB - 1) / TPB, TPB>>>(
        pred_scores, pred_bboxes, anchors, gt_labels, gt_bboxes, pad_mask,
        B, L, C, n);

    output_fused_kernel<<<(BL + TPB - 1) / TPB, TPB>>>(gt_labels, gt_bboxes,
                                                       gt_poses, bg_ptr,
                                                       (float*)d_out,
                                                       B, L, C, n, K);
}

// round 6
// speedup vs baseline: 3.3659x; 1.0380x over previous
#include <cuda_runtime.h>
#include <cuda_bf16.h>
#include <cstdint>

#define EPSV 1e-9f
#define TOPK 13
#define MAXBL (32 * 8400)
#define MAXBN 2048
#define CAP 256
#define TPB 256
#define NCELL 16   // 4x4 spatial grid over [0,640]^2

// ---------------- device scratch (no allocation allowed) ----------------
__device__ unsigned long long g_topk_mask[MAXBL];   // bit j set => anchor i in topk of gt j
__device__ int g_assigned[MAXBL];                   // final single assigned gt (-1 if none)
__device__ float g_align_sel[MAXBL];                // align value at assigned gt
__device__ unsigned int g_max_metrics[MAXBN];       // float bits, per (b, j)
__device__ unsigned int g_max_ious[MAXBN];          // float bits, per (b, j)
__device__ unsigned long long g_cand[(size_t)MAXBN * CAP];  // packed (val, idx) keys
__device__ int g_cnt[MAXBN];                        // candidate count per row

__device__ __forceinline__ int cell_of(float x, float y) {
    int cx = (int)(x * (1.0f / 160.0f));
    int cy = (int)(y * (1.0f / 160.0f));
    cx = max(0, min(3, cx));
    cy = max(0, min(3, cy));
    return cy * 4 + cx;
}

// ---------------- tiny init (per-GT-row arrays only) ----------------
__global__ void init_kernel(int Bn) {
    int i = blockIdx.x * blockDim.x + threadIdx.x;
    if (i < Bn) {
        g_max_metrics[i] = 0u; g_max_ious[i] = 0u;
        g_cnt[i] = 0;
    }
}

// ---------------- kernel A1: candidate compaction (anchor-parallel, bucketed) ----------------
// also zeroes g_topk_mask (each thread owns its anchor's slot)
__global__ __launch_bounds__(TPB) void cand_kernel(
    const float* __restrict__ pred_scores,   // (B,L,C)
    const float* __restrict__ pred_bboxes,   // (B,L,4)
    const float* __restrict__ anchors,       // (L,2)
    const int*   __restrict__ gt_labels,     // (B,n,1)
    const float* __restrict__ gt_bboxes,     // (B,n,4)
    const float* __restrict__ pad_mask,      // (B,n,1)
    int B, int L, int C, int n)
{
    int b = blockIdx.y;
    int i = blockIdx.x * blockDim.x + threadIdx.x;

    // compact non-padded GTs + register into spatial buckets
    __shared__ float4 sgt[64];
    __shared__ int    slab[64];            // label
    __shared__ int    sj[64];              // original j
    __shared__ int    snum;
    __shared__ int    scnt[NCELL];
    __shared__ unsigned char slist[NCELL][64];

    if (threadIdx.x == 0) {
        int m = 0;
        for (int j = 0; j < n; j++) {
            if (pad_mask[b * n + j] > 0.0f) {
                sgt[m]  = ((const float4*)gt_bboxes)[(size_t)b * n + j];
                slab[m] = gt_labels[b * n + j];
                sj[m]   = j;
                m++;
            }
        }
        snum = m;
    }
    if (threadIdx.x < NCELL) scnt[threadIdx.x] = 0;
    __syncthreads();

    if (threadIdx.x < snum) {
        float4 g = sgt[threadIdx.x];
        int cx0 = max(0, min(3, (int)(g.x * (1.0f / 160.0f))));
        int cx1 = max(0, min(3, (int)(g.z * (1.0f / 160.0f))));
        int cy0 = max(0, min(3, (int)(g.y * (1.0f / 160.0f))));
        int cy1 = max(0, min(3, (int)(g.w * (1.0f / 160.0f))));
        for (int cy = cy0; cy <= cy1; cy++)
            for (int cx = cx0; cx <= cx1; cx++) {
                int c = cy * 4 + cx;
                int pos = atomicAdd(&scnt[c], 1);
                slist[c][pos] = (unsigned char)threadIdx.x;
            }
    }
    __syncthreads();
    if (i >= L) return;

    g_topk_mask[(size_t)b * L + i] = 0ull;   // owned slot; set later only by select

    float4 p = ((const float4*)pred_bboxes)[(size_t)b * L + i];
    float parea = (p.z - p.x) * (p.w - p.y);
    float2 a = ((const float2*)anchors)[i];
    const float* psb = pred_scores + ((size_t)b * L + i) * C;

    unsigned int enc_i = 0x7fffffffu - (unsigned int)i;

    int cell = cell_of(a.x, a.y);
    int cn = scnt[cell];

    for (int q = 0; q < cn; q++) {
        int m = slist[cell][q];
        float4 g = sgt[m];
        // exact reference in-gts test: all four deltas > EPS
        bool ing = (a.x - g.x > EPSV) && (a.y - g.y > EPSV) &&
                   (g.z - a.x > EPSV) && (g.w - a.y > EPSV);
        if (!ing) continue;
        float iw = fmaxf(fminf(g.z, p.z) - fmaxf(g.x, p.x), 0.0f);
        float ih = fmaxf(fminf(g.w, p.w) - fmaxf(g.y, p.y), 0.0f);
        float inter = iw * ih;
        float garea = (g.z - g.x) * (g.w - g.y);
        float iou = inter / (garea + parea - inter + EPSV);
        float cls = psb[slab[m]];
        float i2 = iou * iou;
        float v = cls * (i2 * i2 * i2);
        if (v > 0.0f) {
            int row = b * n + sj[m];
            int pos = atomicAdd(&g_cnt[row], 1);
            if (pos < CAP) {
                unsigned long long key =
                    ((unsigned long long)__float_as_uint(v) << 32) | enc_i;
                g_cand[(size_t)row * CAP + pos] = key;
            }
        }
    }
}

// ---------------- kernel A2: per-row top-13 select (one warp per (b,j)) ----------------
// includes inline warp full-L rescan for (essentially never taken) overflow rows
__global__ __launch_bounds__(TPB) void select_kernel(
    const float* __restrict__ pred_scores,
    const float* __restrict__ pred_bboxes,
    const float* __restrict__ anchors,
    const int*   __restrict__ gt_labels,
    const float* __restrict__ gt_bboxes,
    const float* __restrict__ pad_mask,
    int B, int L, int C, int n)
{
    int wid  = threadIdx.x >> 5;
    int lane = threadIdx.x & 31;
    int r = blockIdx.x * (TPB / 32) + wid;
    __shared__ unsigned int bm[TPB / 32][20];   // 640-bit index bitmap per warp
    if (r >= B * n) return;
    if (pad_mask[r] <= 0.0f) return;            // padded row -> no topk bits

    int b = r / n;
    int j = r - b * n;
    unsigned long long jbit = 1ull << j;
    int c = g_cnt[r];

    if (c <= CAP) {
        const unsigned long long* buf = g_cand + (size_t)r * CAP;

        unsigned long long ck[CAP / 32];
        #pragma unroll
        for (int s = 0; s < CAP / 32; s++) {
            int idx = s * 32 + lane;
            ck[s] = (idx < c) ? buf[idx] : 0ull;
        }

        // bitmap of candidate indices < 640 (for exact zero-metric tie fill)
        for (int w = lane; w < 20; w += 32) bm[wid][w] = 0u;
        __syncwarp();
        #pragma unroll
        for (int s = 0; s < CAP / 32; s++) {
            if (ck[s]) {
                unsigned int ai = 0x7fffffffu - (unsigned int)(ck[s] & 0xffffffffu);
                if (ai < 640u) atomicOr(&bm[wid][ai >> 5], 1u << (ai & 31u));
            }
        }
        __syncwarp();

        // up-to-13 rounds of warp argmax (value desc, index asc) over positives
        int p = 0;
        for (int t = 0; t < TOPK; t++) {
            unsigned long long m = 0ull;
            #pragma unroll
            for (int s = 0; s < CAP / 32; s++) if (ck[s] > m) m = ck[s];
            #pragma unroll
            for (int sh = 16; sh > 0; sh >>= 1) {
                unsigned long long o = __shfl_xor_sync(0xffffffffu, m, sh);
                if (o > m) m = o;
            }
            if (m == 0ull) break;       // positives exhausted
            p++;
            #pragma unroll
            for (int s = 0; s < CAP / 32; s++) {
                if (ck[s] == m) {       // keys unique (index embedded)
                    ck[s] = 0ull;
                    unsigned int ai = 0x7fffffffu - (unsigned int)(m & 0xffffffffu);
                    atomicOr(&g_topk_mask[(size_t)b * L + ai], jbit);
                }
            }
        }

        // zero-metric tie fill: smallest indices with metric == 0
        if (lane == 0) {
            int rem = TOPK - p;
            int i = 0;
            while (rem > 0 && i < 640) {
                if (!((bm[wid][i >> 5] >> (i & 31u)) & 1u)) {
                    atomicOr(&g_topk_mask[(size_t)b * L + i], jbit);
                    rem--;
                }
                i++;
            }
        }
        return;
    }

    // ---- overflow fallback: warp-wide full-L rescan (c > CAP > 13 positives,
    // so no zero-tie fill needed) ----
    const float4 g = __ldg((const float4*)gt_bboxes + r);
    const float garea = (g.z - g.x) * (g.w - g.y);
    const int label = gt_labels[r];
    const float4* pb = (const float4*)pred_bboxes + (size_t)b * L;
    const float*  ps = pred_scores + (size_t)b * L * C;
    const float2* ap = (const float2*)anchors;

    float lv[TOPK]; int li[TOPK];
    #pragma unroll
    for (int t = 0; t < TOPK; t++) { lv[t] = -1.0f; li[t] = 0x7fffffff; }

    for (int i = lane; i < L; i += 32) {
        float4 p = pb[i];
        float iw = fmaxf(fminf(g.z, p.z) - fmaxf(g.x, p.x), 0.0f);
        float ih = fmaxf(fminf(g.w, p.w) - fmaxf(g.y, p.y), 0.0f);
        float inter = iw * ih;
        float parea = (p.z - p.x) * (p.w - p.y);
        float iou = inter / (garea + parea - inter + EPSV);
        float cls = ps[(size_t)i * C + label];
        float i2 = iou * iou;
        float align = cls * (i2 * i2 * i2);
        float2 a = ap[i];
        float d = fminf(fminf(a.x - g.x, a.y - g.y), fminf(g.z - a.x, g.w - a.y));
        float v = (d > EPSV) ? align : 0.0f;
        if (v > lv[TOPK - 1]) {
            lv[TOPK - 1] = v; li[TOPK - 1] = i;
            #pragma unroll
            for (int t = TOPK - 1; t > 0; t--) {
                if (lv[t] > lv[t - 1]) {
                    float tv = lv[t]; lv[t] = lv[t - 1]; lv[t - 1] = tv;
                    int   ti = li[t]; li[t] = li[t - 1]; li[t - 1] = ti;
                }
            }
        }
    }

    for (int t = 0; t < TOPK; t++) {
        unsigned long long key =
            ((unsigned long long)__float_as_uint(fmaxf(lv[0], 0.0f)) << 32) |
            (unsigned int)(0x7fffffff - li[0]);
        unsigned long long k = key;
        #pragma unroll
        for (int s = 16; s > 0; s >>= 1) {
            unsigned long long o = __shfl_xor_sync(0xffffffffu, k, s);
            if (o > k) k = o;
        }
        if (key == k && lv[0] >= 0.0f) {   // this lane holds the winner
            atomicOr(&g_topk_mask[(size_t)b * L + li[0]], jbit);
            #pragma unroll
            for (int t2 = 0; t2 < TOPK - 1; t2++) { lv[t2] = lv[t2 + 1]; li[t2] = li[t2 + 1]; }
            lv[TOPK - 1] = -1.0f; li[TOPK - 1] = 0x7fffffff;
        }
        __syncwarp();
    }
}

// ---------------- kernel B: sparse assignment with block work queue ----------------
__global__ __launch_bounds__(TPB) void assign_sparse_kernel(
    const float* __restrict__ pred_scores,
    const float* __restrict__ pred_bboxes,
    const float* __restrict__ anchors,
    const int*   __restrict__ gt_labels,
    const float* __restrict__ gt_bboxes,
    const float* __restrict__ pad_mask,
    int B, int L, int C, int n)
{
    __shared__ unsigned short sq[TPB];
    __shared__ int sqn;
    if (threadIdx.x == 0) sqn = 0;
    __syncthreads();

    size_t BL = (size_t)B * L;
    size_t blockbase = (size_t)blockIdx.x * TPB;
    size_t idx = blockbase + threadIdx.x;

    if (idx < BL) {
        unsigned long long tmask = g_topk_mask[idx];
        g_assigned[idx] = -1;            // default; positives overwritten below
        g_align_sel[idx] = 0.0f;
        if (tmask != 0ull) {
            int p = atomicAdd(&sqn, 1);
            sq[p] = (unsigned short)threadIdx.x;
        }
    }
    __syncthreads();

    int nq = sqn;
    for (int q = threadIdx.x; q < nq; q += TPB) {
        size_t aidx = blockbase + sq[q];
        unsigned long long tmask = g_topk_mask[aidx];   // L1 hit

        int b = (int)(aidx / L);
        int i = (int)(aidx - (size_t)b * L);

        float4 p = ((const float4*)pred_bboxes)[aidx];
        float parea = (p.z - p.x) * (p.w - p.y);
        float2 a = ((const float2*)anchors)[i];
        const float4* gtb = (const float4*)gt_bboxes + (size_t)b * n;
        const float*  pad = pad_mask + (size_t)b * n;

        int cnt = 0, pos_j = -1; float pos_iou = 0.0f;

        unsigned long long m = tmask;
        while (m) {
            int j = __ffsll((long long)m) - 1;
            m &= m - 1;
            float4 g = gtb[j];
            bool ing = (a.x - g.x > EPSV) && (a.y - g.y > EPSV) &&
                       (g.z - a.x > EPSV) && (g.w - a.y > EPSV);
            if (ing && pad[j] > 0.0f) {
                float iw = fmaxf(fminf(g.z, p.z) - fmaxf(g.x, p.x), 0.0f);
                float ih = fmaxf(fminf(g.w, p.w) - fmaxf(g.y, p.y), 0.0f);
                float inter = iw * ih;
                float garea = (g.z - g.x) * (g.w - g.y);
                float iou = inter / (garea + parea - inter + EPSV);
                cnt++; pos_j = j; pos_iou = iou;
            }
        }

        if (cnt == 0) continue;          // tie-fill bits only -> keep background

        int aj; float iou;
        if (cnt == 1) {
            aj = pos_j; iou = pos_iou;
        } else {
            // mps > 1 -> is_max_iou: first argmax of iou over ALL n GTs
            float best_iou = -1.0f; int best_j = 0;
            for (int j = 0; j < n; j++) {
                float4 g = gtb[j];
                float iw = fmaxf(fminf(g.z, p.z) - fmaxf(g.x, p.x), 0.0f);
                float ih = fmaxf(fminf(g.w, p.w) - fmaxf(g.y, p.y), 0.0f);
                float inter = iw * ih;
                float garea = (g.z - g.x) * (g.w - g.y);
                float v = inter / (garea + parea - inter + EPSV);
                if (v > best_iou) { best_iou = v; best_j = j; }
            }
            aj = best_j; iou = best_iou;
        }

        int label = gt_labels[b * n + aj];
        float cls = pred_scores[aidx * C + label];
        float i2 = iou * iou;
        float align = cls * (i2 * i2 * i2);

        g_assigned[aidx] = aj;
        g_align_sel[aidx] = align;
        atomicMax((int*)&g_max_metrics[b * n + aj], __float_as_int(align));
        atomicMax((int*)&g_max_ious[b * n + aj],   __float_as_int(iou));
    }
}

// ---------------- kernel C: fused outputs (scalars + warp-cooperative pose copy) ----------------
__global__ __launch_bounds__(TPB) void output_fused_kernel(
    const int*   __restrict__ gt_labels,
    const float* __restrict__ gt_bboxes,
    const float* __restrict__ gt_poses,
    const int*   __restrict__ bg_ptr,     // may be null
    float* __restrict__ out,
    int B, int L, int C, int n, int K)
{
    size_t BL = (size_t)B * L;
    int lane = threadIdx.x & 31;
    size_t base = ((size_t)blockIdx.x * blockDim.x + (threadIdx.x & ~31)); // warp's first anchor
    size_t idx = base + lane;

    int K3 = K * 3;
    size_t off_lab  = 0;
    size_t off_box  = off_lab + BL;
    size_t off_pose = off_box + 4 * BL;
    size_t off_sc   = off_pose + BL * (size_t)K3;
    size_t off_agi  = off_sc + BL * (size_t)C;

    int bg = bg_ptr ? *bg_ptr : 1;
    int grow = 0;   // gt row for pose gather (b*n + agi)

    if (idx < BL) {
        int b = (int)(idx / L);
        int aj = g_assigned[idx];
        int agi = (aj < 0) ? 0 : aj;
        grow = b * n + agi;
        int label = (aj < 0) ? bg : gt_labels[grow];

        float s = 0.0f;
        if (aj >= 0) {
            float mm = __int_as_float((int)g_max_metrics[grow]);
            float mi = __int_as_float((int)g_max_ious[grow]);
            s = g_align_sel[idx] / (mm + EPSV) * mi;
        }

        out[off_lab + idx] = (float)label;
        ((float4*)(out + off_box))[idx] = ((const float4*)gt_bboxes)[grow];

        float* os = out + off_sc + idx * (size_t)C;
        int m = 0;
        for (int c = 0; c <= C; c++) {
            if (c == bg) continue;
            os[m] = (label == c) ? s : 0.0f;
            m++;
        }
        out[off_agi + idx] = (float)grow;
    }

    // warp-cooperative pose copy: 51 consecutive floats per anchor
    #pragma unroll 1
    for (int m = 0; m < 32; m++) {
        size_t aidx = base + (size_t)m;
        if (aidx >= BL) break;
        int gr = __shfl_sync(0xffffffffu, grow, m);
        const float* gp = gt_poses + (size_t)gr * (size_t)K3;
        float* op = out + off_pose + aidx * (size_t)K3;
        for (int t = lane; t < K3; t += 32) op[t] = gp[t];
    }
}

// ---------------- launcher ----------------
extern "C" void kernel_launch(void* const* d_in, const int* in_sizes, int n_in,
                              void* d_out, int out_size)
{
    const float* pred_scores = (const float*)d_in[0];
    const float* pred_bboxes = (const float*)d_in[1];
    // d_in[2] pred_poses: unused by the reference
    const float* anchors     = (const float*)d_in[3];
    const int*   gt_labels   = (const int*)d_in[4];
    const float* gt_bboxes   = (const float*)d_in[5];
    const float* gt_poses    = (const float*)d_in[6];
    const float* pad_mask    = (const float*)d_in[7];
    const int*   bg_ptr      = (n_in > 8) ? (const int*)d_in[8] : nullptr;

    int L = in_sizes[3] / 2;
    int B = in_sizes[1] / (4 * L);
    int C = in_sizes[0] / (B * L);
    int K = in_sizes[2] / (B * L * 3);
    int n = in_sizes[5] / (B * 4);

    int BL = B * L;
    int Bn = B * n;

    init_kernel<<<(Bn + TPB - 1) / TPB, TPB>>>(Bn);

    dim3 gridA((L + TPB - 1) / TPB, B);
    cand_kernel<<<gridA, TPB>>>(pred_scores, pred_bboxes, anchors,
                                gt_labels, gt_bboxes, pad_mask, B, L, C, n);

    select_kernel<<<(Bn + (TPB / 32) - 1) / (TPB / 32), TPB>>>(
        pred_scores, pred_bboxes, anchors, gt_labels, gt_bboxes, pad_mask,
        B, L, C, n);

    assign_sparse_kernel<<<(BL + TPB - 1) / TPB, TPB>>>(
        pred_scores, pred_bboxes, anchors, gt_labels, gt_bboxes, pad_mask,
        B, L, C, n);

    output_fused_kernel<<<(BL + TPB - 1) / TPB, TPB>>>(gt_labels, gt_bboxes,
                                                       gt_poses, bg_ptr,
                                                       (float*)d_out,
                                                       B, L, C, n, K);
}